// round 1
// baseline (speedup 1.0000x reference)
#include <cuda_runtime.h>

#define B_ 32
#define K_ 64
#define W_ 100
#define H_ 150
#define G_ 450
#define KW_ 6400
#define ALPHA_ 0.2f
#define THRES_ 0.0002f

// ---------------- scratch (__device__ globals; no allocation allowed) ----------------
__device__ float g_Wx[B_*K_*W_];                 // (b*64+s)*100+w
__device__ float g_cx[B_*K_*W_];                 // cause_x
__device__ float g_linT[W_*W_];                  // [i][w]
__device__ float g_glwihT[W_*G_];                // [i][g]
__device__ float2 g_glwhhP[(H_/2)*G_];           // packed pairs over i: [(i/2)][g] = (w_i, w_{i+1})
__device__ float g_muT[H_*H_];                   // [i][o]
__device__ float g_stdT[H_*H_];
__device__ float g_netwihT[K_*W_*G_];            // [k][i][g]
__device__ float g_netwhhT[K_*H_*G_];            // [k][i][g]
__device__ float g_gxg[K_*B_*G_];                // (s*32+b)*450+g
__device__ float g_hl[B_*H_];
__device__ float g_z[B_*H_];
__device__ float g_gxnet[K_*B_*K_*G_];           // (k*2048 + b*64 + s)*450 + g   (236MB)

// ---------------- helpers ----------------
__device__ __forceinline__ unsigned long long pk2(float a, float b){
    unsigned long long r;
    asm("mov.b64 %0, {%1,%2};" : "=l"(r) : "f"(a), "f"(b));
    return r;
}
__device__ __forceinline__ void fma2(unsigned long long &d, unsigned long long a, unsigned long long b){
    asm("fma.rn.f32x2 %0, %1, %2, %0;" : "+l"(d) : "l"(a), "l"(b));
}
__device__ __forceinline__ float2 up2(unsigned long long v){
    float a, b;
    asm("mov.b64 {%0,%1}, %2;" : "=f"(a), "=f"(b) : "l"(v));
    float2 r; r.x = a; r.y = b; return r;
}
__device__ __forceinline__ float sigf(float x){
    return __fdividef(1.f, 1.f + __expf(-x));
}
__device__ __forceinline__ float tanhf_(float x){
    float e = __expf(2.f * x);
    return 1.f - __fdividef(2.f, e + 1.f);
}

// ---------------- prep: transposes / packing ----------------
__global__ void k_prep(const float* lin_w, const float* gl_wih, const float* gl_whh,
                       const float* mu_w, const float* std_w,
                       const float* net_wih, const float* net_whh)
{
    int tid = blockIdx.x * blockDim.x + threadIdx.x;
    int stride = gridDim.x * blockDim.x;
    for (int e = tid; e < W_*W_; e += stride){
        int w = e / W_, i = e % W_;
        g_linT[i*W_ + w] = lin_w[e];
    }
    for (int e = tid; e < G_*W_; e += stride){
        int g = e / W_, i = e % W_;
        g_glwihT[i*G_ + g] = gl_wih[e];
    }
    for (int e = tid; e < (H_/2)*G_; e += stride){
        int i2 = e / G_, g = e % G_;
        float2 v;
        v.x = gl_whh[g*H_ + 2*i2];
        v.y = gl_whh[g*H_ + 2*i2 + 1];
        g_glwhhP[e] = v;
    }
    for (int e = tid; e < H_*H_; e += stride){
        int o = e / H_, i = e % H_;
        g_muT[i*H_ + o]  = mu_w[e];
        g_stdT[i*H_ + o] = std_w[e];
    }
    for (int e = tid; e < K_*G_*W_; e += stride){
        int k = e / (G_*W_); int rem = e % (G_*W_);
        int g = rem / W_, i = rem % W_;
        g_netwihT[k*(W_*G_) + i*G_ + g] = net_wih[e];
    }
    for (int e = tid; e < K_*G_*H_; e += stride){
        int k = e / (G_*H_); int rem = e % (G_*H_);
        int g = rem / H_, i = rem % H_;
        g_netwhhT[k*(H_*G_) + i*G_ + g] = net_whh[e];
    }
}

// ---------------- K1: Wx = x @ lin_w^T + lin_b ----------------
__global__ void k_wx(const float* __restrict__ x, const float* __restrict__ lin_b)
{
    __shared__ float xs[W_];
    int row = blockIdx.x;            // b*64+s, 2048 rows
    int t = threadIdx.x;             // 128
    if (t < W_) xs[t] = x[row*W_ + t];
    __syncthreads();
    if (t < W_){
        float acc = lin_b[t];
        #pragma unroll 4
        for (int i = 0; i < W_; i++) acc += xs[i] * g_linT[i*W_ + t];
        g_Wx[row*W_ + t] = acc;
    }
}

// ---------------- K2: attention scalar + cause_x ----------------
__global__ void k_attn(const float* __restrict__ y, const float* __restrict__ a,
                       const float* __restrict__ bias)
{
    int b = blockIdx.x >> 6;
    int k = blockIdx.x & 63;
    const float a0 = a[0], a1 = a[1];
    const float yb = a0 * y[b*K_ + k];
    const float* vrow = g_Wx + b*KW_;
    const float* brow = bias + k*KW_;
    int t = threadIdx.x;             // 256

    __shared__ float red[256];

    // pass 1: max
    float m = -3.4e38f;
    for (int j = t; j < KW_; j += 256){
        float e = yb + a1*vrow[j] + brow[j];
        e = e > 0.f ? e : ALPHA_*e;
        m = fmaxf(m, e);
    }
    red[t] = m; __syncthreads();
    for (int o = 128; o > 0; o >>= 1){
        if (t < o) red[t] = fmaxf(red[t], red[t+o]);
        __syncthreads();
    }
    float M = red[0]; __syncthreads();

    // pass 2: sumexp
    float ssum = 0.f;
    for (int j = t; j < KW_; j += 256){
        float e = yb + a1*vrow[j] + brow[j];
        e = e > 0.f ? e : ALPHA_*e;
        ssum += __expf(e - M);
    }
    red[t] = ssum; __syncthreads();
    for (int o = 128; o > 0; o >>= 1){
        if (t < o) red[t] += red[t+o];
        __syncthreads();
    }
    float S = red[0]; __syncthreads();

    // threshold in e-space: p >= THRES  <=>  e >= M + ln(THRES*S)
    float T = M + __logf(THRES_ * S);

    float acc = 0.f;
    for (int j = t; j < KW_; j += 256){
        float v = vrow[j];
        float e = yb + a1*v + brow[j];
        e = e > 0.f ? e : ALPHA_*e;
        if (e >= T) acc += v;
    }
    red[t] = acc; __syncthreads();
    for (int o = 128; o > 0; o >>= 1){
        if (t < o) red[t] += red[t+o];
        __syncthreads();
    }
    float sbk = red[0];

    if (t < W_){
        int row = b*K_ + k;
        g_cx[row*W_ + t] = g_Wx[row*W_ + t] + sbk;
    }
}

// ---------------- K3: gx for global GRU ----------------
__global__ void k_gxg(const float* __restrict__ gl_bih)
{
    int s = blockIdx.x >> 5;
    int b = blockIdx.x & 31;
    __shared__ float cx[W_];
    int t = threadIdx.x;             // 512
    if (t < W_) cx[t] = g_cx[(b*K_ + s)*W_ + t];
    __syncthreads();
    if (t < G_){
        float acc = gl_bih[t];
        #pragma unroll 4
        for (int i = 0; i < W_; i++) acc += cx[i] * g_glwihT[i*G_ + t];
        g_gxg[(s*B_ + b)*G_ + t] = acc;
    }
}

// ---------------- K4: global GRU (32 CTAs, one per batch) ----------------
__global__ void k_gru_gl(const float* __restrict__ gl_bhh)
{
    int b = blockIdx.x;
    int t = threadIdx.x;             // 512
    __shared__ __align__(16) float h_sh[152];
    __shared__ float gh_sh[G_];
    if (t < 152) h_sh[t] = 0.f;
    float bhh = (t < G_) ? gl_bhh[t] : 0.f;
    __syncthreads();

    for (int s = 0; s < 64; s++){
        if (t < G_){
            unsigned long long acc = 0ull;
            const unsigned long long* wp = (const unsigned long long*)g_glwhhP;
            const unsigned long long* hp = (const unsigned long long*)h_sh;
            #pragma unroll 5
            for (int i2 = 0; i2 < H_/2; i2++){
                fma2(acc, wp[i2*G_ + t], hp[i2]);
            }
            float2 v = up2(acc);
            gh_sh[t] = v.x + v.y + bhh;
        }
        __syncthreads();
        if (t < H_){
            const float* gx = g_gxg + (s*B_ + b)*G_;
            float r  = sigf(gx[t]        + gh_sh[t]);
            float zz = sigf(gx[H_ + t]   + gh_sh[H_ + t]);
            float n  = tanhf_(gx[2*H_+t] + r * gh_sh[2*H_ + t]);
            h_sh[t] = (1.f - zz)*n + zz*h_sh[t];
        }
        __syncthreads();
    }
    if (t < H_) g_hl[b*H_ + t] = h_sh[t];
}

// ---------------- K5: z = mu + exp(0.5 logvar) * noise ----------------
__global__ void k_z(const float* __restrict__ mu_b, const float* __restrict__ std_b,
                    const float* __restrict__ z_noise)
{
    int b = blockIdx.x, t = threadIdx.x;   // 160
    __shared__ float hs[152];
    if (t < H_) hs[t] = g_hl[b*H_ + t];
    __syncthreads();
    if (t < H_){
        float mu = mu_b[t], lv = std_b[t];
        #pragma unroll 2
        for (int i = 0; i < H_; i++){
            float h = hs[i];
            mu += h * g_muT[i*H_ + t];
            lv += h * g_stdT[i*H_ + t];
        }
        g_z[b*H_ + t] = mu + __expf(0.5f*lv) * z_noise[b*H_ + t];
    }
}

// ---------------- K6: gx for all 64 net GRUs (big GEMM, f32x2) ----------------
__global__ void k_gxnet(const float* __restrict__ net_bih)
{
    int bid = blockIdx.x;            // 8192
    int k = bid >> 7;
    int r0 = (bid & 127) * 16;       // row block (row = b*64+s)
    __shared__ __align__(16) float A_sh[W_*16];
    int t = threadIdx.x;             // 512
    for (int e = t; e < 16*W_; e += 512){
        int rr = e / W_, i = e % W_;
        A_sh[i*16 + rr] = g_Wx[(r0 + rr)*W_ + i];
    }
    __syncthreads();
    if (t < G_){
        const float* wrow = g_netwihT + k*(W_*G_);
        unsigned long long acc[8];
        #pragma unroll
        for (int p = 0; p < 8; p++) acc[p] = 0ull;
        #pragma unroll 2
        for (int i = 0; i < W_; i++){
            float w = wrow[i*G_ + t];
            unsigned long long w2 = pk2(w, w);
            const ulonglong2* hp = (const ulonglong2*)&A_sh[i*16];
            ulonglong2 q0 = hp[0], q1 = hp[1], q2 = hp[2], q3 = hp[3];
            fma2(acc[0], w2, q0.x); fma2(acc[1], w2, q0.y);
            fma2(acc[2], w2, q1.x); fma2(acc[3], w2, q1.y);
            fma2(acc[4], w2, q2.x); fma2(acc[5], w2, q2.y);
            fma2(acc[6], w2, q3.x); fma2(acc[7], w2, q3.y);
        }
        float bi = net_bih[k*G_ + t];
        #pragma unroll
        for (int p = 0; p < 8; p++){
            float2 v = up2(acc[p]);
            g_gxnet[(k*2048 + r0 + 2*p    )*G_ + t] = v.x + bi;
            g_gxnet[(k*2048 + r0 + 2*p + 1)*G_ + t] = v.y + bi;
        }
    }
}

// ---------------- K7: 64 net GRU recurrences (128 CTAs: k x 16-batch) ----------------
__global__ void k_gru_net(const float* __restrict__ net_bhh, float* __restrict__ out)
{
    int k  = blockIdx.x >> 1;
    int b0 = (blockIdx.x & 1) * 16;
    int t = threadIdx.x;             // 512
    __shared__ __align__(16) float h_sh[H_*16];    // [j][bb]
    __shared__ float gh_sh[16*G_];                 // [bb][g]

    for (int e = t; e < H_*16; e += 512){
        int j = e / 16, bb = e % 16;
        h_sh[e] = g_z[(b0 + bb)*H_ + j];
    }
    __syncthreads();

    const float* wrow = g_netwhhT + k*(H_*G_);
    float bhh = (t < G_) ? net_bhh[k*G_ + t] : 0.f;

    for (int s = 0; s < 64; s++){
        if (t < G_){
            unsigned long long acc[8];
            #pragma unroll
            for (int p = 0; p < 8; p++) acc[p] = 0ull;
            #pragma unroll 2
            for (int i = 0; i < H_; i++){
                float w = wrow[i*G_ + t];
                unsigned long long w2 = pk2(w, w);
                const ulonglong2* hp = (const ulonglong2*)&h_sh[i*16];
                ulonglong2 q0 = hp[0], q1 = hp[1], q2 = hp[2], q3 = hp[3];
                fma2(acc[0], w2, q0.x); fma2(acc[1], w2, q0.y);
                fma2(acc[2], w2, q1.x); fma2(acc[3], w2, q1.y);
                fma2(acc[4], w2, q2.x); fma2(acc[5], w2, q2.y);
                fma2(acc[6], w2, q3.x); fma2(acc[7], w2, q3.y);
            }
            #pragma unroll
            for (int p = 0; p < 8; p++){
                float2 v = up2(acc[p]);
                gh_sh[(2*p  )*G_ + t] = v.x + bhh;
                gh_sh[(2*p+1)*G_ + t] = v.y + bhh;
            }
        }
        __syncthreads();
        for (int e = t; e < 16*H_; e += 512){
            int bb = e / H_, j = e % H_;
            const float* gx = g_gxnet + (k*2048 + (b0 + bb)*K_ + s)*G_;
            float ghr = gh_sh[bb*G_ + j];
            float ghz = gh_sh[bb*G_ + H_ + j];
            float ghn = gh_sh[bb*G_ + 2*H_ + j];
            float r  = sigf(gx[j] + ghr);
            float zz = sigf(gx[H_ + j] + ghz);
            float n  = tanhf_(gx[2*H_ + j] + r*ghn);
            float hold = h_sh[j*16 + bb];
            h_sh[j*16 + bb] = (1.f - zz)*n + zz*hold;
        }
        __syncthreads();
    }

    for (int e = t; e < 16*H_; e += 512){
        int bb = e / H_, j = e % H_;
        out[(b0 + bb)*(K_*H_) + k*H_ + j] = h_sh[j*16 + bb];
    }
}

// ---------------- launch ----------------
extern "C" void kernel_launch(void* const* d_in, const int* in_sizes, int n_in,
                              void* d_out, int out_size)
{
    const float* x       = (const float*)d_in[0];
    const float* y       = (const float*)d_in[1];
    const float* z_noise = (const float*)d_in[2];
    const float* lin_w   = (const float*)d_in[3];
    const float* lin_b   = (const float*)d_in[4];
    const float* a       = (const float*)d_in[5];
    const float* bias    = (const float*)d_in[6];
    const float* gl_wih  = (const float*)d_in[7];
    const float* gl_whh  = (const float*)d_in[8];
    const float* gl_bih  = (const float*)d_in[9];
    const float* gl_bhh  = (const float*)d_in[10];
    const float* mu_w    = (const float*)d_in[11];
    const float* mu_b    = (const float*)d_in[12];
    const float* std_w   = (const float*)d_in[13];
    const float* std_b   = (const float*)d_in[14];
    const float* net_wih = (const float*)d_in[15];
    const float* net_whh = (const float*)d_in[16];
    const float* net_bih = (const float*)d_in[17];
    const float* net_bhh = (const float*)d_in[18];
    float* out = (float*)d_out;

    k_prep<<<1024, 256>>>(lin_w, gl_wih, gl_whh, mu_w, std_w, net_wih, net_whh);
    k_wx<<<B_*K_, 128>>>(x, lin_b);
    k_gxnet<<<K_*128, 512>>>(net_bih);          // needs only Wx
    k_attn<<<B_*K_, 256>>>(y, a, bias);
    k_gxg<<<K_*B_, 512>>>(gl_bih);
    k_gru_gl<<<B_, 512>>>(gl_bhh);
    k_z<<<B_, 160>>>(mu_b, std_b, z_noise);
    k_gru_net<<<K_*2, 512>>>(net_bhh, out);
}